// round 7
// baseline (speedup 1.0000x reference)
#include <cuda_runtime.h>

#define PP        4096
#define HH        256
#define NSTEPS    100
#define DTC       0.1f
#define SQRT_DTC  0.31622776601683794f
#define ROWS      16
#define RS        20            // padded act row stride (floats)
#define NTHREADS  256           // 64 col-threads (4 cols each) x 4 k-quarters
#define NBLOCKS   (PP / ROWS)   // 256

// dynamic smem layout (bytes):
// actA 20480 | actB 20480 | partial 32768 | w0 8192 | w3 5120 | b0/b1/b2 3072
// b3 32 | st 128 | inp0 512   => 90784 B  (2 CTAs/SM = 181568 B, fits)
#define SMEM_BYTES 90784

typedef unsigned long long ull;

__device__ __forceinline__ float softplusf(float x) {
    return fmaxf(x, 0.0f) + log1pf(expf(-fabsf(x)));
}
__device__ __forceinline__ ull pack2(float lo, float hi) {
    ull r; asm("mov.b64 %0, {%1, %2};" : "=l"(r) : "f"(lo), "f"(hi)); return r;
}
__device__ __forceinline__ void unpack2(ull v, float& lo, float& hi) {
    asm("mov.b64 {%0, %1}, %2;" : "=f"(lo), "=f"(hi) : "l"(v));
}
__device__ __forceinline__ void fma2(ull& d, ull a, ull b) {
    asm("fma.rn.f32x2 %0, %1, %2, %0;" : "+l"(d) : "l"(a), "l"(b));
}
__device__ __forceinline__ ull add2(ull a, ull b) {
    ull r; asm("add.rn.f32x2 %0, %1, %2;" : "=l"(r) : "l"(a), "l"(b)); return r;
}

// One 256->256 layer + relu. act/nxt: [col][row], stride RS, 16 rows.
// Thread (t = tid&63, q = tid>>6): cols 4t..4t+3, k-quarter [64q, 64q+64).
// Per k: 1 LDG.128 + 4 broadcast LDS.128 + 32 FFMA2.
// Reduction: all quarters dump to partial; thread (q,t) reduces col 4t+q.
// Two phases of 16 accs each keep the partial buffer at 32KB.
__device__ __forceinline__ void mlp_layer(const float* act, float* nxt,
                                          const float4* __restrict__ wp,
                                          const float* b_sh, ull* partial,
                                          int t, int q) {
    ull acc[4][8];
#pragma unroll
    for (int c = 0; c < 4; c++)
#pragma unroll
        for (int i = 0; i < 8; i++) acc[c][i] = 0ull;

    const float* ab = act + q * 64 * RS;
#pragma unroll 4
    for (int k = 0; k < 64; k++) {
        float4 wv = __ldg(wp + k * (HH / 4));
        ull w0 = pack2(wv.x, wv.x);
        ull w1 = pack2(wv.y, wv.y);
        ull w2 = pack2(wv.z, wv.z);
        ull w3 = pack2(wv.w, wv.w);
        const ulonglong2* ar = reinterpret_cast<const ulonglong2*>(ab + k * RS);
        ulonglong2 a0 = ar[0], a1 = ar[1], a2 = ar[2], a3 = ar[3];
        fma2(acc[0][0], a0.x, w0); fma2(acc[0][1], a0.y, w0);
        fma2(acc[0][2], a1.x, w0); fma2(acc[0][3], a1.y, w0);
        fma2(acc[0][4], a2.x, w0); fma2(acc[0][5], a2.y, w0);
        fma2(acc[0][6], a3.x, w0); fma2(acc[0][7], a3.y, w0);
        fma2(acc[1][0], a0.x, w1); fma2(acc[1][1], a0.y, w1);
        fma2(acc[1][2], a1.x, w1); fma2(acc[1][3], a1.y, w1);
        fma2(acc[1][4], a2.x, w1); fma2(acc[1][5], a2.y, w1);
        fma2(acc[1][6], a3.x, w1); fma2(acc[1][7], a3.y, w1);
        fma2(acc[2][0], a0.x, w2); fma2(acc[2][1], a0.y, w2);
        fma2(acc[2][2], a1.x, w2); fma2(acc[2][3], a1.y, w2);
        fma2(acc[2][4], a2.x, w2); fma2(acc[2][5], a2.y, w2);
        fma2(acc[2][6], a3.x, w2); fma2(acc[2][7], a3.y, w2);
        fma2(acc[3][0], a0.x, w3); fma2(acc[3][1], a0.y, w3);
        fma2(acc[3][2], a1.x, w3); fma2(acc[3][3], a1.y, w3);
        fma2(acc[3][4], a2.x, w3); fma2(acc[3][5], a2.y, w3);
        fma2(acc[3][6], a3.x, w3); fma2(acc[3][7], a3.y, w3);
    }

    const int bq = q * 64 + t;
    const int col = 4 * t + q;
    const float bb = b_sh[col];
#pragma unroll
    for (int ph = 0; ph < 2; ph++) {
#pragma unroll
        for (int c = 0; c < 4; c++)
#pragma unroll
            for (int j = 0; j < 4; j++)
                partial[((c * 4 + j) << 8) + bq] = acc[c][ph * 4 + j];
        __syncthreads();
#pragma unroll
        for (int j = 0; j < 4; j++) {
            const int slot = ((q * 4 + j) << 8) + t;
            ull v = add2(partial[slot], partial[slot + 64]);
            v = add2(v, add2(partial[slot + 128], partial[slot + 192]));
            float lo, hi; unpack2(v, lo, hi);
            lo = fmaxf(lo + bb, 0.0f);
            hi = fmaxf(hi + bb, 0.0f);
            *reinterpret_cast<ull*>(nxt + col * RS + 2 * (ph * 4 + j)) = pack2(lo, hi);
        }
        __syncthreads();
    }
}

__global__ void __launch_bounds__(NTHREADS, 2) lv_kernel(
    const float* __restrict__ W0, const float* __restrict__ b0,
    const float* __restrict__ W1, const float* __restrict__ b1,
    const float* __restrict__ W2, const float* __restrict__ b2,
    const float* __restrict__ W3, const float* __restrict__ b3,
    const float* __restrict__ obs_init, const float* __restrict__ feature_init,
    const float* __restrict__ tn_store, const float* __restrict__ x1_store,
    const float* __restrict__ x2_store, const float* __restrict__ path_seed,
    float* __restrict__ out) {
    extern __shared__ __align__(16) unsigned char smem_raw[];
    float* actA = reinterpret_cast<float*>(smem_raw);                 // 5120 f
    float* actB = actA + HH * RS;                                     // 5120 f
    ull*   partial = reinterpret_cast<ull*>(actB + HH * RS);          // 4096 ull
    float* w0_sh = reinterpret_cast<float*>(partial + 4096);          // 2048 f
    float* w3_sh = w0_sh + 8 * HH;                                    // 1280 f
    float* b0_sh = w3_sh + HH * 5;                                    // 256 f
    float* b1_sh = b0_sh + HH;                                        // 256 f
    float* b2_sh = b1_sh + HH;                                        // 256 f
    float* b3_sh = b2_sh + HH;                                        // 8 f
    float* st_sh = b3_sh + 8;                                         // 32 f
    float* inp0_sh = st_sh + 32;                                      // 128 f

    const int tid  = threadIdx.x;
    const int row0 = blockIdx.x * ROWS;
    const int t    = tid & 63;
    const int q    = tid >> 6;

    // ---- one-time staging ----
    for (int i = tid; i < 8 * HH; i += NTHREADS) w0_sh[i] = W0[i];
    for (int i = tid; i < HH * 5; i += NTHREADS) w3_sh[i] = W3[i];
    if (tid < HH) { b0_sh[tid] = b0[tid]; b1_sh[tid] = b1[tid]; b2_sh[tid] = b2[tid]; }
    if (tid < 5) b3_sh[tid] = b3[tid];
    if (tid < ROWS * 2) st_sh[tid] = obs_init[row0 * 2 + tid];
    if (tid < ROWS * 8) {
        int r = tid >> 3, k = tid & 7;
        inp0_sh[tid] = (k < 2) ? obs_init[(row0 + r) * 2 + k]
                               : feature_init[(row0 + r) * 6 + (k - 2)];
    }
    float t_reg = __ldg(feature_init);   // t0 = feature_init[0,0,0]
    __syncthreads();

    const float4* wp1 = reinterpret_cast<const float4*>(W1) + q * 64 * (HH / 4) + t;
    const float4* wp2 = reinterpret_cast<const float4*>(W2) + q * 64 * (HH / 4) + t;

    // layer-3 mapping: warp w -> rows 2w, 2w+1 (half-warp each), 16-way split-K
    const int warp = tid >> 5, lane = tid & 31;
    const int l3r = 2 * warp + (lane >> 4);
    const int l3l = lane & 15;

#pragma unroll 1
    for (int s = 0; s < NSTEPS; s++) {
        // ---- layer 0: (16 x 8) @ (8 x 256) + relu -> actA[n][r], col n = tid
        if (s == 0) {
            float a;
#pragma unroll
            for (int r = 0; r < ROWS; r++) {
                a = b0_sh[tid];
#pragma unroll
                for (int k = 0; k < 8; k++)
                    a = fmaf(inp0_sh[r * 8 + k], w0_sh[k * HH + tid], a);
                actA[tid * RS + r] = fmaxf(a, 0.0f);
            }
        } else {
            t_reg += DTC;   // exact sequential fp32 accumulation
            const int i = s - 1;
            const float f_tn = __ldg(tn_store + i);
            const float f_x1 = __ldg(x1_store + i);
            const float f_x2 = __ldg(x2_store + i);
            // features are row-uniform: fold them once
            float base = b0_sh[tid];
            base = fmaf(t_reg, w0_sh[2 * HH + tid], base);
            base = fmaf(f_tn,  w0_sh[3 * HH + tid], base);
            base = fmaf(f_x1,  w0_sh[4 * HH + tid], base);
            base = fmaf(f_x2,  w0_sh[5 * HH + tid], base);
            base = fmaf(f_x1,  w0_sh[6 * HH + tid], base);
            base = fmaf(f_x2,  w0_sh[7 * HH + tid], base);
            const float wa = w0_sh[tid], wb = w0_sh[HH + tid];
#pragma unroll
            for (int r = 0; r < ROWS; r++) {
                float a = fmaf(st_sh[2 * r], wa, fmaf(st_sh[2 * r + 1], wb, base));
                actA[tid * RS + r] = fmaxf(a, 0.0f);
            }
        }
        __syncthreads();

        mlp_layer(actA, actB, wp1, b1_sh, partial, t, q);
        mlp_layer(actB, actA, wp2, b2_sh, partial, t, q);

        // ---- layer 3: (16 x 256) @ (256 x 5), half-warp per row, 16-way split-K
        float acc5[5] = {0.f, 0.f, 0.f, 0.f, 0.f};
#pragma unroll
        for (int kk = 0; kk < 16; kk++) {
            int k = l3l + (kk << 4);
            float a = actA[k * RS + l3r];
#pragma unroll
            for (int m = 0; m < 5; m++) acc5[m] = fmaf(a, w3_sh[k * 5 + m], acc5[m]);
        }
#pragma unroll
        for (int off = 8; off >= 1; off >>= 1) {
#pragma unroll
            for (int m = 0; m < 5; m++)
                acc5[m] += __shfl_down_sync(0xffffffffu, acc5[m], off, 16);
        }

        if (l3l == 0) {
            const int r = l3r;
            const int p = row0 + r;
            float mu0 = acc5[0] + b3_sh[0];
            float mu1 = acc5[1] + b3_sh[1];
            float s11 = softplusf(acc5[2] + b3_sh[2]);
            float s21 = acc5[3] + b3_sh[3];
            float s22 = softplusf(acc5[4] + b3_sh[4]);
            float st0 = st_sh[2 * r], st1 = st_sh[2 * r + 1];
            float2 e = __ldg(reinterpret_cast<const float2*>(path_seed) + s * PP + p);
            float n0v = softplusf(st0 + DTC * mu0 + SQRT_DTC * (s11 * e.x));
            float n1v = softplusf(st1 + DTC * mu1 + SQRT_DTC * (s21 * e.x + s22 * e.y));
            st_sh[2 * r]     = n0v;
            st_sh[2 * r + 1] = n1v;

            // path: out[p*202 + d*101 + time]; step s writes time = s+1
            out[p * 202 + (s + 1)]       = n0v;
            out[p * 202 + 101 + (s + 1)] = n1v;
            if (s == 0) {
                out[p * 202 + 0]   = st0;
                out[p * 202 + 101] = st1;
            }
            int mb = PP * 202 + (p * 100 + s) * 2;
            out[mb + 0] = mu0;
            out[mb + 1] = mu1;
            int sb = PP * 202 + PP * 200 + (p * 100 + s) * 4;
            out[sb + 0] = s11;
            out[sb + 1] = 0.0f;
            out[sb + 2] = s21;
            out[sb + 3] = s22;
        }
        __syncthreads();
    }
}

extern "C" void kernel_launch(void* const* d_in, const int* in_sizes, int n_in,
                              void* d_out, int out_size) {
    const float* W0 = (const float*)d_in[0];
    const float* b0 = (const float*)d_in[1];
    const float* W1 = (const float*)d_in[2];
    const float* b1 = (const float*)d_in[3];
    const float* W2 = (const float*)d_in[4];
    const float* b2 = (const float*)d_in[5];
    const float* W3 = (const float*)d_in[6];
    const float* b3 = (const float*)d_in[7];
    const float* obs_init = (const float*)d_in[8];
    const float* feature_init = (const float*)d_in[9];
    const float* tn_store = (const float*)d_in[10];
    const float* x1_store = (const float*)d_in[11];
    const float* x2_store = (const float*)d_in[12];
    const float* path_seed = (const float*)d_in[13];
    float* out = (float*)d_out;

    cudaFuncSetAttribute(lv_kernel, cudaFuncAttributeMaxDynamicSharedMemorySize,
                         SMEM_BYTES);
    lv_kernel<<<NBLOCKS, NTHREADS, SMEM_BYTES>>>(
        W0, b0, W1, b1, W2, b2, W3, b3, obs_init, feature_init,
        tn_store, x1_store, x2_store, path_seed, out);
}

// round 8
// speedup vs baseline: 1.9326x; 1.9326x over previous
#include <cuda_runtime.h>
#include <cuda_bf16.h>
#include <cstdint>

#define PP        4096
#define HH        256
#define NSTEPS    100
#define DTC       0.1f
#define SQRT_DTC  0.31622776601683794f
#define M_CTA     32
#define NCTA      (PP / M_CTA)   // 128
#define NTHREADS  256
#define AS        264            // bf16 row stride (528B) for act tiles: conflict-free ldsm

// smem: 4 act bufs (67584) + w0 (8192) + b0/b1/b2 (3072) + b3 (32)
//       + out5 (1024) + st (256) + inp0 (1024) = 81184
#define SMEM_BYTES 81184

// Weight fragments in exact mma.m16n8k16 B-operand order: [k_tile][n8][lane] -> {b0,b1}
__device__ uint2 g_W1h[16 * 32 * 32];
__device__ uint2 g_W1l[16 * 32 * 32];
__device__ uint2 g_W2h[16 * 32 * 32];
__device__ uint2 g_W2l[16 * 32 * 32];
__device__ uint2 g_W3h[16 * 32];
__device__ uint2 g_W3l[16 * 32];

__device__ __forceinline__ float softplusf(float x) {
    return fmaxf(x, 0.0f) + log1pf(expf(-fabsf(x)));
}
__device__ __forceinline__ uint32_t bfpack(float a, float b) {
    __nv_bfloat162 v = __floats2bfloat162_rn(a, b);   // .x = a (low half)
    return *reinterpret_cast<uint32_t*>(&v);
}

// ---------------- prep: fp32 weights -> hi/lo bf16 fragment arrays ----------------
__global__ void prep_kernel(const float* __restrict__ W1,
                            const float* __restrict__ W2,
                            const float* __restrict__ W3) {
    const int idx = blockIdx.x * blockDim.x + threadIdx.x;
    const int TOT = 16 * 32 * 32;
    if (idx < 2 * TOT) {
        const int l = idx / TOT, r = idx % TOT;
        const int kt = r >> 10;
        const int n8 = (r >> 5) & 31;
        const int lane = r & 31;
        const int k0 = kt * 16 + (lane & 3) * 2;
        const int n = n8 * 8 + (lane >> 2);
        const float* W = l ? W2 : W1;
        float x[4];
        x[0] = W[(k0)     * HH + n];
        x[1] = W[(k0 + 1) * HH + n];
        x[2] = W[(k0 + 8) * HH + n];
        x[3] = W[(k0 + 9) * HH + n];
        float h[4], lo[4];
#pragma unroll
        for (int i = 0; i < 4; i++) {
            h[i]  = __bfloat162float(__float2bfloat16(x[i]));
            lo[i] = x[i] - h[i];
        }
        uint2 hv, lv;
        hv.x = bfpack(h[0], h[1]);  hv.y = bfpack(h[2], h[3]);
        lv.x = bfpack(lo[0], lo[1]); lv.y = bfpack(lo[2], lo[3]);
        if (l) { g_W2h[r] = hv; g_W2l[r] = lv; }
        else   { g_W1h[r] = hv; g_W1l[r] = lv; }
    } else if (idx < 2 * TOT + 512) {
        const int r = idx - 2 * TOT;
        const int kt = r >> 5, lane = r & 31;
        const int k0 = kt * 16 + (lane & 3) * 2;
        const int n = lane >> 2;
        float x[4] = {0.f, 0.f, 0.f, 0.f};
        if (n < 5) {
            x[0] = W3[(k0)     * 5 + n];
            x[1] = W3[(k0 + 1) * 5 + n];
            x[2] = W3[(k0 + 8) * 5 + n];
            x[3] = W3[(k0 + 9) * 5 + n];
        }
        float h[4], lo[4];
#pragma unroll
        for (int i = 0; i < 4; i++) {
            h[i]  = __bfloat162float(__float2bfloat16(x[i]));
            lo[i] = x[i] - h[i];
        }
        uint2 hv, lv;
        hv.x = bfpack(h[0], h[1]);  hv.y = bfpack(h[2], h[3]);
        lv.x = bfpack(lo[0], lo[1]); lv.y = bfpack(lo[2], lo[3]);
        g_W3h[r] = hv; g_W3l[r] = lv;
    }
}

// ---------------- tensor-core primitives ----------------
__device__ __forceinline__ void ldsm4(uint32_t* r, const __nv_bfloat16* p) {
    uint32_t addr = (uint32_t)__cvta_generic_to_shared(p);
    asm volatile("ldmatrix.sync.aligned.m8n8.x4.shared.b16 {%0,%1,%2,%3}, [%4];"
                 : "=r"(r[0]), "=r"(r[1]), "=r"(r[2]), "=r"(r[3]) : "r"(addr));
}
__device__ __forceinline__ void mma_bf16(float* d, const uint32_t* a,
                                         uint32_t b0, uint32_t b1) {
    asm volatile(
        "mma.sync.aligned.m16n8k16.row.col.f32.bf16.bf16.f32 "
        "{%0,%1,%2,%3}, {%4,%5,%6,%7}, {%8,%9}, {%0,%1,%2,%3};"
        : "+f"(d[0]), "+f"(d[1]), "+f"(d[2]), "+f"(d[3])
        : "r"(a[0]), "r"(a[1]), "r"(a[2]), "r"(a[3]), "r"(b0), "r"(b1));
}

// One 256->256 layer + bias + relu, 3-term split-bf16.
// Warp w owns output cols [32w, 32w+32). A hi/lo read from smem via ldmatrix;
// B fragments stream straight from L2 (coalesced LDG.64 per lane).
__device__ __forceinline__ void tc_layer(
    const __nv_bfloat16* Ah, const __nv_bfloat16* Al,
    __nv_bfloat16* Oh, __nv_bfloat16* Ol,
    const uint2* __restrict__ Bh, const uint2* __restrict__ Bl,
    const float* b_sh, int warp, int lane) {
    float D[2][4][4];
#pragma unroll
    for (int mt = 0; mt < 2; mt++)
#pragma unroll
        for (int nt = 0; nt < 4; nt++)
#pragma unroll
            for (int i = 0; i < 4; i++) D[mt][nt][i] = 0.0f;

    const int arow = (lane & 7) + ((lane >> 3) & 1) * 8;
    const int acol = (lane >> 4) * 8;
#pragma unroll 4
    for (int kt = 0; kt < 16; kt++) {
        uint32_t ah0[4], ah1[4], al0[4], al1[4];
        const int co = kt * 16 + acol;
        ldsm4(ah0, Ah + arow * AS + co);
        ldsm4(ah1, Ah + (arow + 16) * AS + co);
        ldsm4(al0, Al + arow * AS + co);
        ldsm4(al1, Al + (arow + 16) * AS + co);
        const uint2* bhp = Bh + (kt * 32 + 4 * warp) * 32 + lane;
        const uint2* blp = Bl + (kt * 32 + 4 * warp) * 32 + lane;
#pragma unroll
        for (int nt = 0; nt < 4; nt++) {
            uint2 bh = __ldg(bhp + nt * 32);
            uint2 bl = __ldg(blp + nt * 32);
            mma_bf16(D[0][nt], ah0, bh.x, bh.y);
            mma_bf16(D[1][nt], ah1, bh.x, bh.y);
            mma_bf16(D[0][nt], ah0, bl.x, bl.y);
            mma_bf16(D[1][nt], ah1, bl.x, bl.y);
            mma_bf16(D[0][nt], al0, bh.x, bh.y);
            mma_bf16(D[1][nt], al1, bh.x, bh.y);
        }
    }

    // epilogue: bias + relu + hi/lo split, conflict-free STS.32
    const int rbase = lane >> 2;
#pragma unroll
    for (int mt = 0; mt < 2; mt++) {
#pragma unroll
        for (int nt = 0; nt < 4; nt++) {
            const int col = (4 * warp + nt) * 8 + (lane & 3) * 2;
            const float bb0 = b_sh[col], bb1 = b_sh[col + 1];
#pragma unroll
            for (int h = 0; h < 2; h++) {
                const int row = mt * 16 + rbase + h * 8;
                float x0 = fmaxf(D[mt][nt][2 * h + 0] + bb0, 0.0f);
                float x1 = fmaxf(D[mt][nt][2 * h + 1] + bb1, 0.0f);
                float h0 = __bfloat162float(__float2bfloat16(x0));
                float h1 = __bfloat162float(__float2bfloat16(x1));
                *reinterpret_cast<uint32_t*>(Oh + row * AS + col) = bfpack(h0, h1);
                *reinterpret_cast<uint32_t*>(Ol + row * AS + col) =
                    bfpack(x0 - h0, x1 - h1);
            }
        }
    }
}

// ---------------- main persistent kernel ----------------
__global__ void __launch_bounds__(NTHREADS, 1) lv_tc_kernel(
    const float* __restrict__ W0, const float* __restrict__ b0,
    const float* __restrict__ b1, const float* __restrict__ b2,
    const float* __restrict__ b3,
    const float* __restrict__ obs_init, const float* __restrict__ feature_init,
    const float* __restrict__ tn_store, const float* __restrict__ x1_store,
    const float* __restrict__ x2_store, const float* __restrict__ path_seed,
    float* __restrict__ out) {
    extern __shared__ __align__(16) unsigned char smem_raw[];
    __nv_bfloat16* Ah = reinterpret_cast<__nv_bfloat16*>(smem_raw);
    __nv_bfloat16* Al = Ah + 32 * AS;
    __nv_bfloat16* Bh = Al + 32 * AS;
    __nv_bfloat16* Bl = Bh + 32 * AS;
    float* w0_sh = reinterpret_cast<float*>(Bl + 32 * AS);
    float* b0_sh = w0_sh + 8 * HH;
    float* b1_sh = b0_sh + HH;
    float* b2_sh = b1_sh + HH;
    float* b3_sh = b2_sh + HH;       // 8
    float* out5  = b3_sh + 8;        // 32*8
    float* st_sh = out5 + 32 * 8;    // 64
    float* inp0  = st_sh + 64;       // 32*8

    const int tid = threadIdx.x;
    const int warp = tid >> 5, lane = tid & 31;
    const int row0 = blockIdx.x * M_CTA;

    // one-time staging
    for (int i = tid; i < 8 * HH; i += NTHREADS) w0_sh[i] = W0[i];
    if (tid < HH) { b0_sh[tid] = b0[tid]; b1_sh[tid] = b1[tid]; b2_sh[tid] = b2[tid]; }
    if (tid < 8) b3_sh[tid] = (tid < 5) ? b3[tid] : 0.0f;
    if (tid < 64) st_sh[tid] = obs_init[row0 * 2 + tid];
    if (tid < 32 * 8) {
        int r = tid >> 3, k = tid & 7;
        inp0[tid] = (k < 2) ? obs_init[(row0 + r) * 2 + k]
                            : feature_init[(row0 + r) * 6 + (k - 2)];
    }
    float t_reg = __ldg(feature_init);   // t0 = feature_init[0,0,0]
    __syncthreads();

#pragma unroll 1
    for (int s = 0; s < NSTEPS; s++) {
        // ---- layer 0 (scalar fp32): col n = tid, 32 rows -> Ah/Al
        {
            const int n = tid;
            if (s == 0) {
#pragma unroll 4
                for (int r = 0; r < 32; r++) {
                    float a = b0_sh[n];
#pragma unroll
                    for (int k = 0; k < 8; k++)
                        a = fmaf(inp0[r * 8 + k], w0_sh[k * HH + n], a);
                    a = fmaxf(a, 0.0f);
                    float h = __bfloat162float(__float2bfloat16(a));
                    Ah[r * AS + n] = __float2bfloat16(a);
                    Al[r * AS + n] = __float2bfloat16(a - h);
                }
            } else {
                t_reg += DTC;   // exact sequential fp32 time accumulation
                const int i = s - 1;
                const float f_tn = __ldg(tn_store + i);
                const float f_x1 = __ldg(x1_store + i);
                const float f_x2 = __ldg(x2_store + i);
                float base = b0_sh[n];
                base = fmaf(t_reg, w0_sh[2 * HH + n], base);
                base = fmaf(f_tn,  w0_sh[3 * HH + n], base);
                base = fmaf(f_x1,  w0_sh[4 * HH + n], base);
                base = fmaf(f_x2,  w0_sh[5 * HH + n], base);
                base = fmaf(f_x1,  w0_sh[6 * HH + n], base);
                base = fmaf(f_x2,  w0_sh[7 * HH + n], base);
                const float wa = w0_sh[n], wb = w0_sh[HH + n];
#pragma unroll 4
                for (int r = 0; r < 32; r++) {
                    float a = fmaf(st_sh[2 * r], wa, fmaf(st_sh[2 * r + 1], wb, base));
                    a = fmaxf(a, 0.0f);
                    float h = __bfloat162float(__float2bfloat16(a));
                    Ah[r * AS + n] = __float2bfloat16(a);
                    Al[r * AS + n] = __float2bfloat16(a - h);
                }
            }
        }
        __syncthreads();

        tc_layer(Ah, Al, Bh, Bl, g_W1h, g_W1l, b1_sh, warp, lane);
        __syncthreads();
        tc_layer(Bh, Bl, Ah, Al, g_W2h, g_W2l, b2_sh, warp, lane);
        __syncthreads();

        // ---- layer 3: (32 x 256) @ (256 x 5pad8), warps 0-1 (one m16 tile each)
        if (warp < 2) {
            float D[4] = {0.f, 0.f, 0.f, 0.f};
            const int arow = warp * 16 + (lane & 7) + ((lane >> 3) & 1) * 8;
            const int acol = (lane >> 4) * 8;
#pragma unroll 4
            for (int kt = 0; kt < 16; kt++) {
                uint32_t ah[4], al[4];
                ldsm4(ah, Ah + arow * AS + kt * 16 + acol);
                ldsm4(al, Al + arow * AS + kt * 16 + acol);
                uint2 bh = __ldg(&g_W3h[kt * 32 + lane]);
                uint2 bl = __ldg(&g_W3l[kt * 32 + lane]);
                mma_bf16(D, ah, bh.x, bh.y);
                mma_bf16(D, ah, bl.x, bl.y);
                mma_bf16(D, al, bh.x, bh.y);
            }
            const int row = warp * 16 + (lane >> 2);
            const int col = (lane & 3) * 2;
            out5[row * 8 + col]           = D[0];
            out5[row * 8 + col + 1]       = D[1];
            out5[(row + 8) * 8 + col]     = D[2];
            out5[(row + 8) * 8 + col + 1] = D[3];
        }
        __syncthreads();

        // ---- SDE sample + global writes (fp32, exact reference semantics)
        if (tid < 32) {
            const int r = tid, p = row0 + r;
            float mu0 = out5[r * 8 + 0] + b3_sh[0];
            float mu1 = out5[r * 8 + 1] + b3_sh[1];
            float s11 = softplusf(out5[r * 8 + 2] + b3_sh[2]);
            float s21 = out5[r * 8 + 3] + b3_sh[3];
            float s22 = softplusf(out5[r * 8 + 4] + b3_sh[4]);
            float st0 = st_sh[2 * r], st1 = st_sh[2 * r + 1];
            float2 e = __ldg(reinterpret_cast<const float2*>(path_seed) + s * PP + p);
            float n0v = softplusf(st0 + DTC * mu0 + SQRT_DTC * (s11 * e.x));
            float n1v = softplusf(st1 + DTC * mu1 + SQRT_DTC * (s21 * e.x + s22 * e.y));
            st_sh[2 * r]     = n0v;
            st_sh[2 * r + 1] = n1v;

            out[p * 202 + (s + 1)]       = n0v;
            out[p * 202 + 101 + (s + 1)] = n1v;
            if (s == 0) {
                out[p * 202 + 0]   = st0;
                out[p * 202 + 101] = st1;
            }
            int mb = PP * 202 + (p * 100 + s) * 2;
            out[mb + 0] = mu0;
            out[mb + 1] = mu1;
            int sb = PP * 202 + PP * 200 + (p * 100 + s) * 4;
            out[sb + 0] = s11;
            out[sb + 1] = 0.0f;
            out[sb + 2] = s21;
            out[sb + 3] = s22;
        }
        __syncthreads();
    }
}

extern "C" void kernel_launch(void* const* d_in, const int* in_sizes, int n_in,
                              void* d_out, int out_size) {
    const float* W0 = (const float*)d_in[0];
    const float* b0 = (const float*)d_in[1];
    const float* W1 = (const float*)d_in[2];
    const float* b1 = (const float*)d_in[3];
    const float* W2 = (const float*)d_in[4];
    const float* b2 = (const float*)d_in[5];
    const float* W3 = (const float*)d_in[6];
    const float* b3 = (const float*)d_in[7];
    const float* obs_init = (const float*)d_in[8];
    const float* feature_init = (const float*)d_in[9];
    const float* tn_store = (const float*)d_in[10];
    const float* x1_store = (const float*)d_in[11];
    const float* x2_store = (const float*)d_in[12];
    const float* path_seed = (const float*)d_in[13];
    float* out = (float*)d_out;

    // 1) split weights into hi/lo bf16 fragment arrays (2*16384 + 512 slots)
    prep_kernel<<<130, 256>>>(W1, W2, W3);

    // 2) persistent 100-step trajectory kernel
    cudaFuncSetAttribute(lv_tc_kernel, cudaFuncAttributeMaxDynamicSharedMemorySize,
                         SMEM_BYTES);
    lv_tc_kernel<<<NCTA, NTHREADS, SMEM_BYTES>>>(
        W0, b0, b1, b2, b3, obs_init, feature_init,
        tn_store, x1_store, x2_store, path_seed, out);
}

// round 10
// speedup vs baseline: 2.3437x; 1.2127x over previous
#include <cuda_runtime.h>
#include <cuda_bf16.h>
#include <cstdint>

#define PP        4096
#define HH        256
#define NSTEPS    100
#define DTC       0.1f
#define SQRT_DTC  0.31622776601683794f
#define M_CTA     32
#define NCTA      (PP / M_CTA)   // 128
#define NTHREADS  256
#define AS        264            // bf16 row stride (528B): conflict-free ldsm/STS

// smem: 4 act bufs (67584) + w0 (8192) + b0/b1/b2 (3072) + b3 (32)
//       + out5 (1024) + st (256) + inp0 (1024) + w3frag (8192) = 89376
#define SMEM_BYTES 89376

// Weight fragments in exact mma.m16n8k16 B-operand order: [k_tile][n8][lane] -> {b0,b1}
__device__ uint2 g_W1h[16 * 32 * 32];
__device__ uint2 g_W1l[16 * 32 * 32];
__device__ uint2 g_W2h[16 * 32 * 32];
__device__ uint2 g_W2l[16 * 32 * 32];
__device__ uint2 g_W3h[16 * 32];
__device__ uint2 g_W3l[16 * 32];

__device__ __forceinline__ float softplusf(float x) {
    return fmaxf(x, 0.0f) + log1pf(expf(-fabsf(x)));
}
__device__ __forceinline__ uint32_t bfpack(float a, float b) {
    __nv_bfloat162 v = __floats2bfloat162_rn(a, b);   // .x = a (low half)
    return *reinterpret_cast<uint32_t*>(&v);
}

// ---------------- prep: fp32 weights -> hi/lo bf16 fragment arrays ----------------
__global__ void prep_kernel(const float* __restrict__ W1,
                            const float* __restrict__ W2,
                            const float* __restrict__ W3) {
    const int idx = blockIdx.x * blockDim.x + threadIdx.x;
    const int TOT = 16 * 32 * 32;
    if (idx < 2 * TOT) {
        const int l = idx / TOT, r = idx % TOT;
        const int kt = r >> 10;
        const int n8 = (r >> 5) & 31;
        const int lane = r & 31;
        const int k0 = kt * 16 + (lane & 3) * 2;
        const int n = n8 * 8 + (lane >> 2);
        const float* W = l ? W2 : W1;
        float x[4];
        x[0] = W[(k0)     * HH + n];
        x[1] = W[(k0 + 1) * HH + n];
        x[2] = W[(k0 + 8) * HH + n];
        x[3] = W[(k0 + 9) * HH + n];
        float h[4], lo[4];
#pragma unroll
        for (int i = 0; i < 4; i++) {
            h[i]  = __bfloat162float(__float2bfloat16(x[i]));
            lo[i] = x[i] - h[i];
        }
        uint2 hv, lv;
        hv.x = bfpack(h[0], h[1]);  hv.y = bfpack(h[2], h[3]);
        lv.x = bfpack(lo[0], lo[1]); lv.y = bfpack(lo[2], lo[3]);
        if (l) { g_W2h[r] = hv; g_W2l[r] = lv; }
        else   { g_W1h[r] = hv; g_W1l[r] = lv; }
    } else if (idx < 2 * TOT + 512) {
        const int r = idx - 2 * TOT;
        const int kt = r >> 5, lane = r & 31;
        const int k0 = kt * 16 + (lane & 3) * 2;
        const int n = lane >> 2;
        float x[4] = {0.f, 0.f, 0.f, 0.f};
        if (n < 5) {
            x[0] = W3[(k0)     * 5 + n];
            x[1] = W3[(k0 + 1) * 5 + n];
            x[2] = W3[(k0 + 8) * 5 + n];
            x[3] = W3[(k0 + 9) * 5 + n];
        }
        float h[4], lo[4];
#pragma unroll
        for (int i = 0; i < 4; i++) {
            h[i]  = __bfloat162float(__float2bfloat16(x[i]));
            lo[i] = x[i] - h[i];
        }
        uint2 hv, lv;
        hv.x = bfpack(h[0], h[1]);  hv.y = bfpack(h[2], h[3]);
        lv.x = bfpack(lo[0], lo[1]); lv.y = bfpack(lo[2], lo[3]);
        g_W3h[r] = hv; g_W3l[r] = lv;
    }
}

// ---------------- tensor-core primitives ----------------
__device__ __forceinline__ void ldsm4(uint32_t* r, const __nv_bfloat16* p) {
    uint32_t addr = (uint32_t)__cvta_generic_to_shared(p);
    asm volatile("ldmatrix.sync.aligned.m8n8.x4.shared.b16 {%0,%1,%2,%3}, [%4];"
                 : "=r"(r[0]), "=r"(r[1]), "=r"(r[2]), "=r"(r[3]) : "r"(addr));
}
__device__ __forceinline__ void mma_bf16(float* d, const uint32_t* a,
                                         uint32_t b0, uint32_t b1) {
    asm volatile(
        "mma.sync.aligned.m16n8k16.row.col.f32.bf16.bf16.f32 "
        "{%0,%1,%2,%3}, {%4,%5,%6,%7}, {%8,%9}, {%0,%1,%2,%3};"
        : "+f"(d[0]), "+f"(d[1]), "+f"(d[2]), "+f"(d[3])
        : "r"(a[0]), "r"(a[1]), "r"(a[2]), "r"(a[3]), "r"(b0), "r"(b1));
}

// fragment bundle for one kt: A hi/lo (2 m-tiles) + B hi/lo (4 n-tiles)
struct Frag {
    uint32_t ah0[4], ah1[4], al0[4], al1[4];
    uint2 bh[4], bl[4];
};

__device__ __forceinline__ void load_frag(
    Frag& f, const __nv_bfloat16* Ah, const __nv_bfloat16* Al,
    const uint2* __restrict__ bhp, const uint2* __restrict__ blp,
    int arow, int co, int kt) {
    ldsm4(f.ah0, Ah + arow * AS + co);
    ldsm4(f.ah1, Ah + (arow + 16) * AS + co);
    ldsm4(f.al0, Al + arow * AS + co);
    ldsm4(f.al1, Al + (arow + 16) * AS + co);
    const uint2* bh = bhp + kt * 1024;
    const uint2* bl = blp + kt * 1024;
#pragma unroll
    for (int nt = 0; nt < 4; nt++) {
        f.bh[nt] = __ldg(bh + nt * 32);
        f.bl[nt] = __ldg(bl + nt * 32);
    }
}

__device__ __forceinline__ void mma_frag(float D[2][4][4], const Frag& f) {
#pragma unroll
    for (int nt = 0; nt < 4; nt++) {
        mma_bf16(D[0][nt], f.ah0, f.bh[nt].x, f.bh[nt].y);
        mma_bf16(D[1][nt], f.ah1, f.bh[nt].x, f.bh[nt].y);
        mma_bf16(D[0][nt], f.ah0, f.bl[nt].x, f.bl[nt].y);
        mma_bf16(D[1][nt], f.ah1, f.bl[nt].x, f.bl[nt].y);
        mma_bf16(D[0][nt], f.al0, f.bh[nt].x, f.bh[nt].y);
        mma_bf16(D[1][nt], f.al1, f.bh[nt].x, f.bh[nt].y);
    }
}

// One 256->256 layer + bias + relu, 3-term split-bf16, double-buffered pipeline.
__device__ __forceinline__ void tc_layer(
    const __nv_bfloat16* Ah, const __nv_bfloat16* Al,
    __nv_bfloat16* Oh, __nv_bfloat16* Ol,
    const uint2* __restrict__ Bh, const uint2* __restrict__ Bl,
    const float* b_sh, int warp, int lane) {
    float D[2][4][4];
#pragma unroll
    for (int mt = 0; mt < 2; mt++)
#pragma unroll
        for (int nt = 0; nt < 4; nt++)
#pragma unroll
            for (int i = 0; i < 4; i++) D[mt][nt][i] = 0.0f;

    const int arow = (lane & 7) + ((lane >> 3) & 1) * 8;
    const int acol = (lane >> 4) * 8;
    const uint2* bhp = Bh + 4 * warp * 32 + lane;   // + kt*1024 per tile
    const uint2* blp = Bl + 4 * warp * 32 + lane;

    Frag f0, f1;
    load_frag(f0, Ah, Al, bhp, blp, arow, acol, 0);
#pragma unroll 2
    for (int i = 0; i < 8; i++) {
        const int kt = 2 * i;
        // prefetch kt+1, compute kt
        load_frag(f1, Ah, Al, bhp, blp, arow, (kt + 1) * 16 + acol, kt + 1);
        mma_frag(D, f0);
        // prefetch kt+2, compute kt+1
        if (i < 7)
            load_frag(f0, Ah, Al, bhp, blp, arow, (kt + 2) * 16 + acol, kt + 2);
        mma_frag(D, f1);
    }

    // epilogue: bias + relu + hi/lo split, conflict-free STS.32
    const int rbase = lane >> 2;
#pragma unroll
    for (int mt = 0; mt < 2; mt++) {
#pragma unroll
        for (int nt = 0; nt < 4; nt++) {
            const int col = (4 * warp + nt) * 8 + (lane & 3) * 2;
            const float bb0 = b_sh[col], bb1 = b_sh[col + 1];
#pragma unroll
            for (int h = 0; h < 2; h++) {
                const int row = mt * 16 + rbase + h * 8;
                float x0 = fmaxf(D[mt][nt][2 * h + 0] + bb0, 0.0f);
                float x1 = fmaxf(D[mt][nt][2 * h + 1] + bb1, 0.0f);
                float h0 = __bfloat162float(__float2bfloat16(x0));
                float h1 = __bfloat162float(__float2bfloat16(x1));
                *reinterpret_cast<uint32_t*>(Oh + row * AS + col) = bfpack(h0, h1);
                *reinterpret_cast<uint32_t*>(Ol + row * AS + col) =
                    bfpack(x0 - h0, x1 - h1);
            }
        }
    }
}

// ---------------- main persistent kernel ----------------
__global__ void __launch_bounds__(NTHREADS, 1) lv_tc_kernel(
    const float* __restrict__ W0, const float* __restrict__ b0,
    const float* __restrict__ b1, const float* __restrict__ b2,
    const float* __restrict__ b3,
    const float* __restrict__ obs_init, const float* __restrict__ feature_init,
    const float* __restrict__ tn_store, const float* __restrict__ x1_store,
    const float* __restrict__ x2_store, const float* __restrict__ path_seed,
    float* __restrict__ out) {
    extern __shared__ __align__(16) unsigned char smem_raw[];
    __nv_bfloat16* Ah = reinterpret_cast<__nv_bfloat16*>(smem_raw);
    __nv_bfloat16* Al = Ah + 32 * AS;
    __nv_bfloat16* Bh = Al + 32 * AS;
    __nv_bfloat16* Bl = Bh + 32 * AS;
    float* w0_sh = reinterpret_cast<float*>(Bl + 32 * AS);
    float* b0_sh = w0_sh + 8 * HH;
    float* b1_sh = b0_sh + HH;
    float* b2_sh = b1_sh + HH;
    float* b3_sh = b2_sh + HH;       // 8
    float* out5  = b3_sh + 8;        // 32*8
    float* st_sh = out5 + 32 * 8;    // 64
    float* inp0  = st_sh + 64;       // 32*8
    uint2* w3f   = reinterpret_cast<uint2*>(inp0 + 32 * 8);  // 1024 uint2 = 8192 B

    const int tid = threadIdx.x;
    const int warp = tid >> 5, lane = tid & 31;
    const int row0 = blockIdx.x * M_CTA;

    // one-time staging
    for (int i = tid; i < 8 * HH; i += NTHREADS) w0_sh[i] = W0[i];
    if (tid < HH) { b0_sh[tid] = b0[tid]; b1_sh[tid] = b1[tid]; b2_sh[tid] = b2[tid]; }
    if (tid < 8) b3_sh[tid] = (tid < 5) ? b3[tid] : 0.0f;
    if (tid < 64) st_sh[tid] = obs_init[row0 * 2 + tid];
    if (tid < 32 * 8) {
        int r = tid >> 3, k = tid & 7;
        inp0[tid] = (k < 2) ? obs_init[(row0 + r) * 2 + k]
                            : feature_init[(row0 + r) * 6 + (k - 2)];
    }
    // layer-3 fragments -> smem once: hi at [0,512), lo at [512,1024)
    for (int i = tid; i < 1024; i += NTHREADS)
        w3f[i] = (i < 512) ? g_W3h[i] : g_W3l[i - 512];
    float t_reg = __ldg(feature_init);   // t0 = feature_init[0,0,0]
    __syncthreads();

#pragma unroll 1
    for (int s = 0; s < NSTEPS; s++) {
        // ---- layer 0 (scalar fp32): col n = tid, 32 rows -> Ah/Al
        {
            const int n = tid;
            if (s == 0) {
#pragma unroll 4
                for (int r = 0; r < 32; r++) {
                    float a = b0_sh[n];
#pragma unroll
                    for (int k = 0; k < 8; k++)
                        a = fmaf(inp0[r * 8 + k], w0_sh[k * HH + n], a);
                    a = fmaxf(a, 0.0f);
                    float h = __bfloat162float(__float2bfloat16(a));
                    Ah[r * AS + n] = __float2bfloat16(a);
                    Al[r * AS + n] = __float2bfloat16(a - h);
                }
            } else {
                t_reg += DTC;   // exact sequential fp32 time accumulation
                const int i = s - 1;
                const float f_tn = __ldg(tn_store + i);
                const float f_x1 = __ldg(x1_store + i);
                const float f_x2 = __ldg(x2_store + i);
                float base = b0_sh[n];
                base = fmaf(t_reg, w0_sh[2 * HH + n], base);
                base = fmaf(f_tn,  w0_sh[3 * HH + n], base);
                base = fmaf(f_x1,  w0_sh[4 * HH + n], base);
                base = fmaf(f_x2,  w0_sh[5 * HH + n], base);
                base = fmaf(f_x1,  w0_sh[6 * HH + n], base);
                base = fmaf(f_x2,  w0_sh[7 * HH + n], base);
                const float wa = w0_sh[n], wb = w0_sh[HH + n];
#pragma unroll 4
                for (int r = 0; r < 32; r++) {
                    float a = fmaf(st_sh[2 * r], wa, fmaf(st_sh[2 * r + 1], wb, base));
                    a = fmaxf(a, 0.0f);
                    float h = __bfloat162float(__float2bfloat16(a));
                    Ah[r * AS + n] = __float2bfloat16(a);
                    Al[r * AS + n] = __float2bfloat16(a - h);
                }
            }
        }
        __syncthreads();

        tc_layer(Ah, Al, Bh, Bl, g_W1h, g_W1l, b1_sh, warp, lane);
        __syncthreads();
        tc_layer(Bh, Bl, Ah, Al, g_W2h, g_W2l, b2_sh, warp, lane);
        __syncthreads();

        // ---- layer 3: (32 x 256) @ (256 x 5pad8), warps 0-1 (one m16 tile each)
        if (warp < 2) {
            float D[4] = {0.f, 0.f, 0.f, 0.f};
            const int arow = warp * 16 + (lane & 7) + ((lane >> 3) & 1) * 8;
            const int acol = (lane >> 4) * 8;
#pragma unroll
            for (int kt = 0; kt < 16; kt++) {
                uint32_t ah[4], al[4];
                ldsm4(ah, Ah + arow * AS + kt * 16 + acol);
                ldsm4(al, Al + arow * AS + kt * 16 + acol);
                uint2 bh = w3f[kt * 32 + lane];
                uint2 bl = w3f[512 + kt * 32 + lane];
                mma_bf16(D, ah, bh.x, bh.y);
                mma_bf16(D, ah, bl.x, bl.y);
                mma_bf16(D, al, bh.x, bh.y);
            }
            const int row = warp * 16 + (lane >> 2);
            const int col = (lane & 3) * 2;
            out5[row * 8 + col]           = D[0];
            out5[row * 8 + col + 1]       = D[1];
            out5[(row + 8) * 8 + col]     = D[2];
            out5[(row + 8) * 8 + col + 1] = D[3];
        }
        __syncthreads();

        // ---- SDE sample + global writes (fp32, exact reference semantics)
        if (tid < 32) {
            const int r = tid, p = row0 + r;
            float mu0 = out5[r * 8 + 0] + b3_sh[0];
            float mu1 = out5[r * 8 + 1] + b3_sh[1];
            float s11 = softplusf(out5[r * 8 + 2] + b3_sh[2]);
            float s21 = out5[r * 8 + 3] + b3_sh[3];
            float s22 = softplusf(out5[r * 8 + 4] + b3_sh[4]);
            float st0 = st_sh[2 * r], st1 = st_sh[2 * r + 1];
            float2 e = __ldg(reinterpret_cast<const float2*>(path_seed) + s * PP + p);
            float n0v = softplusf(st0 + DTC * mu0 + SQRT_DTC * (s11 * e.x));
            float n1v = softplusf(st1 + DTC * mu1 + SQRT_DTC * (s21 * e.x + s22 * e.y));
            st_sh[2 * r]     = n0v;
            st_sh[2 * r + 1] = n1v;

            out[p * 202 + (s + 1)]       = n0v;
            out[p * 202 + 101 + (s + 1)] = n1v;
            if (s == 0) {
                out[p * 202 + 0]   = st0;
                out[p * 202 + 101] = st1;
            }
            int mb = PP * 202 + (p * 100 + s) * 2;
            out[mb + 0] = mu0;
            out[mb + 1] = mu1;
            int sb = PP * 202 + PP * 200 + (p * 100 + s) * 4;
            out[sb + 0] = s11;
            out[sb + 1] = 0.0f;
            out[sb + 2] = s21;
            out[sb + 3] = s22;
        }
        __syncthreads();
    }
}

extern "C" void kernel_launch(void* const* d_in, const int* in_sizes, int n_in,
                              void* d_out, int out_size) {
    const float* W0 = (const float*)d_in[0];
    const float* b0 = (const float*)d_in[1];
    const float* W1 = (const float*)d_in[2];
    const float* b1 = (const float*)d_in[3];
    const float* W2 = (const float*)d_in[4];
    const float* b2 = (const float*)d_in[5];
    const float* W3 = (const float*)d_in[6];
    const float* b3 = (const float*)d_in[7];
    const float* obs_init = (const float*)d_in[8];
    const float* feature_init = (const float*)d_in[9];
    const float* tn_store = (const float*)d_in[10];
    const float* x1_store = (const float*)d_in[11];
    const float* x2_store = (const float*)d_in[12];
    const float* path_seed = (const float*)d_in[13];
    float* out = (float*)d_out;

    // 1) split weights into hi/lo bf16 fragment arrays
    prep_kernel<<<130, 256>>>(W1, W2, W3);

    // 2) persistent 100-step trajectory kernel
    cudaFuncSetAttribute(lv_tc_kernel, cudaFuncAttributeMaxDynamicSharedMemorySize,
                         SMEM_BYTES);
    lv_tc_kernel<<<NCTA, NTHREADS, SMEM_BYTES>>>(
        W0, b0, b1, b2, b3, obs_init, feature_init,
        tn_store, x1_store, x2_store, path_seed, out);
}